// round 4
// baseline (speedup 1.0000x reference)
#include <cuda_runtime.h>
#include <cstdint>

#define NMAX 100000
#define EMAX 600000
#define GMAX 4096
#define H 128
#define FIN 74

// ---------------- scratch (device globals; no allocations allowed) ----------------
__device__ __align__(16) float d_h [(size_t)NMAX * H];   // current features
__device__ __align__(16) float d_hw[(size_t)NMAX * H];   // h @ W
__device__ __align__(16) float d_hn[(size_t)NMAX * H];   // aggregated messages
__device__ __align__(16) float d_dinv[NMAX];             // deg -> rsqrt(deg)
__device__ __align__(16) float d_bnstats[2 * H];         // sum, sumsq
__device__ __align__(16) float d_scale[2 * H];           // scale, shift
__device__ __align__(16) float d_gsum[(size_t)GMAX * H];
__device__ __align__(16) int   d_gmax[(size_t)GMAX * H];
__device__ __align__(16) float d_gcnt[GMAX];

// ---------------- degree / normalization ----------------
__global__ void deg_init_kernel(int N) {
    int i = blockIdx.x * blockDim.x + threadIdx.x;
    if (i < N) d_dinv[i] = 1.0f;  // self-loop
}
__global__ void deg_edge_kernel(const int* __restrict__ ei, int E) {
    int i = blockIdx.x * blockDim.x + threadIdx.x;
    if (i < E) atomicAdd(&d_dinv[ei[E + i]], 1.0f);  // dst degree
}
__global__ void deg_fin_kernel(int N) {
    int i = blockIdx.x * blockDim.x + threadIdx.x;
    if (i < N) d_dinv[i] = rsqrtf(d_dinv[i]);
}
__global__ void zero_stats_kernel() {
    if (threadIdx.x < 2 * H) d_bnstats[threadIdx.x] = 0.0f;
}

// ---------------- GEMM: C[N][128] = A[N][K] @ B[K][128] ----------------
// 64-row tile per block, 256 threads, each thread computes 8 rows x 4 cols.
// MODE 0: emb     -> C = relu(A@B + bias)
// MODE 1: conv    -> d_hw = A@B ; d_hn = (A@B)*dinv[row]^2 + convb
template<int MODE>
__global__ void __launch_bounds__(256)
gemm_kernel(const float* __restrict__ A, const float* __restrict__ B,
            const float* __restrict__ bias, float* __restrict__ C, int N, int K) {
    extern __shared__ float sm[];
    const int lda = K + 4;
    float* As = sm;             // [64][K+4]
    float* Bs = sm + 64 * lda;  // [K][128]
    int tid = threadIdx.x;
    int rowBase = blockIdx.x * 64;

    for (int i = tid; i < K * H; i += 256) Bs[i] = B[i];
    for (int i = tid; i < 64 * K; i += 256) {
        int r = i / K, k = i - r * K;
        int gr = rowBase + r;
        As[r * lda + k] = (gr < N) ? A[(size_t)gr * K + k] : 0.0f;
    }
    __syncthreads();

    int tx = tid & 31;   // cols 4*tx .. 4*tx+3
    int ty = tid >> 5;   // rows 8*ty .. 8*ty+7
    const float* Arow = As + (ty * 8) * lda;
    const float4* Bv = (const float4*)Bs;

    float acc[8][4];
#pragma unroll
    for (int i = 0; i < 8; i++) { acc[i][0] = acc[i][1] = acc[i][2] = acc[i][3] = 0.0f; }

#pragma unroll 4
    for (int k = 0; k < K; k++) {
        float4 b4 = Bv[k * 32 + tx];
#pragma unroll
        for (int i = 0; i < 8; i++) {
            float a = Arow[i * lda + k];  // warp-broadcast
            acc[i][0] = fmaf(a, b4.x, acc[i][0]);
            acc[i][1] = fmaf(a, b4.y, acc[i][1]);
            acc[i][2] = fmaf(a, b4.z, acc[i][2]);
            acc[i][3] = fmaf(a, b4.w, acc[i][3]);
        }
    }

    float4 bb = ((const float4*)bias)[tx];
#pragma unroll
    for (int i = 0; i < 8; i++) {
        int gr = rowBase + ty * 8 + i;
        if (gr >= N) continue;
        if (MODE == 0) {
            float4 o;
            o.x = fmaxf(acc[i][0] + bb.x, 0.f);
            o.y = fmaxf(acc[i][1] + bb.y, 0.f);
            o.z = fmaxf(acc[i][2] + bb.z, 0.f);
            o.w = fmaxf(acc[i][3] + bb.w, 0.f);
            *(float4*)&C[(size_t)gr * H + tx * 4] = o;
        } else {
            float4 hw = make_float4(acc[i][0], acc[i][1], acc[i][2], acc[i][3]);
            *(float4*)&d_hw[(size_t)gr * H + tx * 4] = hw;
            float dv = d_dinv[gr];
            float w = dv * dv;
            float4 o;
            o.x = fmaf(hw.x, w, bb.x); o.y = fmaf(hw.y, w, bb.y);
            o.z = fmaf(hw.z, w, bb.z); o.w = fmaf(hw.w, w, bb.w);
            *(float4*)&d_hn[(size_t)gr * H + tx * 4] = o;
        }
    }
}

// ---------------- edge scatter: h_next[dst] += hw[src]*norm (warp per edge) ----------------
__global__ void scatter_kernel(const int* __restrict__ ei, int E) {
    unsigned i = blockIdx.x * blockDim.x + threadIdx.x;
    unsigned e = i >> 5;
    if (e >= (unsigned)E) return;
    int lane = i & 31;
    int s = ei[e];
    int d = ei[E + e];
    float nrm = d_dinv[s] * d_dinv[d];
    float4 v = ((const float4*)d_hw)[(size_t)s * 32 + lane];
    float* dst = d_hn + (size_t)d * H + lane * 4;
    asm volatile("red.global.add.v4.f32 [%0], {%1,%2,%3,%4};"
                 :: "l"(dst), "f"(v.x * nrm), "f"(v.y * nrm), "f"(v.z * nrm), "f"(v.w * nrm)
                 : "memory");
}

// ---------------- BatchNorm stats (sum, sumsq per channel) ----------------
__global__ void bn_stats_kernel(int N) {
    int c = threadIdx.x & (H - 1);
    int half = threadIdx.x >> 7;  // 0/1
    int base = blockIdx.x * 512;
    int end = min(base + 512, N);
    float s = 0.0f, q = 0.0f;
    for (int r = base + half; r < end; r += 2) {
        float v = d_hn[(size_t)r * H + c];
        s += v; q += v * v;
    }
    __shared__ float sh[512];
    sh[threadIdx.x] = s;
    sh[256 + threadIdx.x] = q;
    __syncthreads();
    if (threadIdx.x < H) {
        atomicAdd(&d_bnstats[c], sh[c] + sh[H + c]);
        atomicAdd(&d_bnstats[H + c], sh[256 + c] + sh[256 + H + c]);
    }
}

__global__ void bn_finalize_kernel(const float* __restrict__ gamma,
                                   const float* __restrict__ beta, float invN) {
    int c = threadIdx.x;
    float mean = d_bnstats[c] * invN;
    float var = d_bnstats[H + c] * invN - mean * mean;
    float sc = gamma[c] * rsqrtf(var + 1e-5f);
    d_scale[c] = sc;
    d_scale[H + c] = beta[c] - mean * sc;
}

__global__ void bn_apply_kernel(int n4) {
    int i = blockIdx.x * blockDim.x + threadIdx.x;
    if (i >= n4) return;
    int c4 = i & 31;
    float4 v  = ((const float4*)d_hn)[i];
    float4 sc = ((const float4*)d_scale)[c4];
    float4 sh = ((const float4*)d_scale)[32 + c4];
    float4 o;
    o.x = fmaxf(fmaf(v.x, sc.x, sh.x), 0.f);
    o.y = fmaxf(fmaf(v.y, sc.y, sh.y), 0.f);
    o.z = fmaxf(fmaf(v.z, sc.z, sh.z), 0.f);
    o.w = fmaxf(fmaf(v.w, sc.w, sh.w), 0.f);
    ((float4*)d_h)[i] = o;
}

// ---------------- pooling (mean + max per graph) ----------------
__global__ void pool_init_kernel(int G) {
    int i = blockIdx.x * blockDim.x + threadIdx.x;
    if (i < G * H) { d_gsum[i] = 0.0f; d_gmax[i] = 0; }  // 0 == __float_as_int(0.0f)
    if (i < G) d_gcnt[i] = 0.0f;
}

__global__ void pool_kernel(const int* __restrict__ batch, int N) {
    unsigned i = blockIdx.x * blockDim.x + threadIdx.x;
    unsigned n = i >> 5;
    if (n >= (unsigned)N) return;
    int lane = i & 31;
    int b = batch[n];
    float4 v = ((const float4*)d_h)[(size_t)n * 32 + lane];
    float* dst = d_gsum + (size_t)b * H + lane * 4;
    asm volatile("red.global.add.v4.f32 [%0], {%1,%2,%3,%4};"
                 :: "l"(dst), "f"(v.x), "f"(v.y), "f"(v.z), "f"(v.w) : "memory");
    int* mdst = d_gmax + (size_t)b * H + lane * 4;
    atomicMax(mdst + 0, __float_as_int(v.x));  // values >= 0 post-ReLU: int order == float order
    atomicMax(mdst + 1, __float_as_int(v.y));
    atomicMax(mdst + 2, __float_as_int(v.z));
    atomicMax(mdst + 3, __float_as_int(v.w));
    if (lane == 0) atomicAdd(&d_gcnt[b], 1.0f);
}

// ---------------- MLP head: one block per graph ----------------
__global__ void __launch_bounds__(128)
mlp_kernel(const float* __restrict__ w1, const float* __restrict__ b1,
           const float* __restrict__ w2, const float* __restrict__ b2,
           const float* __restrict__ w3, const float* __restrict__ b3,
           float* __restrict__ out) {
    int g = blockIdx.x, t = threadIdx.x;
    __shared__ float gs[2 * H], h1s[H], h2s[64];
    float inv = 1.0f / fmaxf(d_gcnt[g], 1.0f);
    gs[t]     = d_gsum[(size_t)g * H + t] * inv;
    gs[H + t] = __int_as_float(d_gmax[(size_t)g * H + t]);
    __syncthreads();
    float a = b1[t];
#pragma unroll 8
    for (int k = 0; k < 2 * H; k++) a = fmaf(gs[k], w1[k * H + t], a);
    h1s[t] = fmaxf(a, 0.0f);
    __syncthreads();
    if (t < 64) {
        float a2 = b2[t];
#pragma unroll 8
        for (int k = 0; k < H; k++) a2 = fmaf(h1s[k], w2[k * 64 + t], a2);
        h2s[t] = fmaxf(a2, 0.0f);
    }
    __syncthreads();
    if (t < 32) {
        float s = h2s[t] * w3[t] + h2s[t + 32] * w3[t + 32];
        for (int o = 16; o; o >>= 1) s += __shfl_down_sync(0xffffffffu, s, o);
        if (t == 0) out[g] = s + b3[0];
    }
}

// ---------------- launch ----------------
extern "C" void kernel_launch(void* const* d_in, const int* in_sizes, int n_in,
                              void* d_out, int out_size) {
    const float* x      = (const float*)d_in[0];
    const int*   ei     = (const int*)  d_in[1];
    const int*   batch  = (const int*)  d_in[2];
    const float* emb_W  = (const float*)d_in[3];
    const float* emb_b  = (const float*)d_in[4];
    const float* conv_W = (const float*)d_in[5];
    const float* conv_b = (const float*)d_in[6];
    const float* bn_g   = (const float*)d_in[7];
    const float* bn_b   = (const float*)d_in[8];
    const float* w1     = (const float*)d_in[9];
    const float* b1     = (const float*)d_in[10];
    const float* w2     = (const float*)d_in[11];
    const float* b2     = (const float*)d_in[12];
    const float* w3     = (const float*)d_in[13];
    const float* b3     = (const float*)d_in[14];
    float* out = (float*)d_out;

    int N = in_sizes[0] / FIN;
    int E = in_sizes[1] / 2;
    int G = out_size;
    int n4 = N * 32;  // float4 count of an [N,128] buffer

    float *ph = nullptr;
    cudaGetSymbolAddress((void**)&ph, d_h);

    size_t embSm  = (size_t)(64 * (FIN + 4) + FIN * H) * sizeof(float);  // ~57 KB
    size_t convSm = (size_t)(64 * (H + 4) + H * H) * sizeof(float);      // ~97 KB
    cudaFuncSetAttribute(gemm_kernel<0>,
                         cudaFuncAttributeMaxDynamicSharedMemorySize, (int)embSm);
    cudaFuncSetAttribute(gemm_kernel<1>,
                         cudaFuncAttributeMaxDynamicSharedMemorySize, (int)convSm);

    // degrees & normalization
    deg_init_kernel<<<(N + 255) / 256, 256>>>(N);
    deg_edge_kernel<<<(E + 255) / 256, 256>>>(ei, E);
    deg_fin_kernel<<<(N + 255) / 256, 256>>>(N);

    // embedding
    gemm_kernel<0><<<(N + 63) / 64, 256, embSm>>>(x, emb_W, emb_b, ph, N, FIN);

    // GCN layers
    for (int l = 0; l < 3; l++) {
        // conv GEMM with fused self-loop/bias epilogue: writes d_hw and d_hn
        gemm_kernel<1><<<(N + 63) / 64, 256, convSm>>>(
            ph, conv_W + (size_t)l * H * H, conv_b + (size_t)l * H, nullptr, N, H);
        scatter_kernel<<<(E * 32 + 255) / 256, 256>>>(ei, E);
        zero_stats_kernel<<<1, 256>>>();
        bn_stats_kernel<<<(N + 511) / 512, 256>>>(N);
        bn_finalize_kernel<<<1, H>>>(bn_g + l * H, bn_b + l * H, 1.0f / (float)N);
        bn_apply_kernel<<<(n4 + 255) / 256, 256>>>(n4);
    }

    // pooling + head
    pool_init_kernel<<<(G * H + 255) / 256, 256>>>(G);
    pool_kernel<<<(n4 + 255) / 256, 256>>>(batch, N);
    mlp_kernel<<<G, H>>>(w1, b1, w2, b2, w3, b3, out);
}

// round 5
// speedup vs baseline: 1.1541x; 1.1541x over previous
#include <cuda_runtime.h>
#include <cstdint>

#define NMAX 100000
#define EMAX 600000
#define GMAX 4096
#define H 128
#define FIN 74

// ---------------- scratch (device globals; no allocations allowed) ----------------
__device__ __align__(16) float d_h [(size_t)NMAX * H];   // emb output
__device__ __align__(16) float d_hw[(size_t)NMAX * H];   // h @ W
__device__ __align__(16) float d_hn[(size_t)NMAX * H];   // aggregated messages (pre-BN)
__device__ __align__(16) float d_dinv[NMAX];             // deg -> rsqrt(deg)
__device__ __align__(16) float d_bnstats[2 * H];         // sum, sumsq
__device__ __align__(16) float d_scale[2 * H];           // scale, shift
__device__ __align__(16) float d_gsum[(size_t)GMAX * H];
__device__ __align__(16) int   d_gmax[(size_t)GMAX * H];
__device__ __align__(16) float d_gcnt[GMAX];

// ---------------- degree / normalization ----------------
__global__ void deg_init_kernel(int N) {
    int i = blockIdx.x * blockDim.x + threadIdx.x;
    if (i < N) d_dinv[i] = 1.0f;  // self-loop
}
__global__ void deg_edge_kernel(const int* __restrict__ ei, int E) {
    int i = blockIdx.x * blockDim.x + threadIdx.x;
    if (i < E) atomicAdd(&d_dinv[ei[E + i]], 1.0f);  // dst degree
}
__global__ void deg_fin_kernel(int N) {
    int i = blockIdx.x * blockDim.x + threadIdx.x;
    if (i < N) d_dinv[i] = rsqrtf(d_dinv[i]);
}
__global__ void zero_stats_kernel() {
    if (threadIdx.x < 2 * H) d_bnstats[threadIdx.x] = 0.0f;
}

// ---------------- GEMM: C[N][128] = A[N][K] @ B[K][128] ----------------
// 64-row tile per block, 256 threads, each thread computes 8 rows x 4 cols.
// Inner loop vectorized over k (float4 A and B loads -> FFMA density 0.91).
// MODE 0: emb  (K=74, scalar A load) -> C = relu(A@B + bias)
// MODE 1: conv (K=128, float4 A load, optional fused BN+ReLU on A load)
//              -> d_hw = A@B ; d_hn = (A@B)*dinv[row]^2 + bias
template<int MODE, bool BNA>
__global__ void __launch_bounds__(256)
gemm_kernel(const float* __restrict__ A, const float* __restrict__ B,
            const float* __restrict__ bias, float* __restrict__ C,
            int N, int K, int Kp, int lda) {
    extern __shared__ float sm[];
    float* As = sm;              // [64][lda]
    float* Bs = sm + 64 * lda;   // [Kp][128]
    int tid = threadIdx.x;
    int rowBase = blockIdx.x * 64;

    // B tile (zero-padded to Kp rows)
    {
        const float4* Bg = (const float4*)B;
        float4* Bsh = (float4*)Bs;
        int tot = Kp * 32;
        for (int i = tid; i < tot; i += 256) {
            int k = i >> 5;
            float4 v = make_float4(0.f, 0.f, 0.f, 0.f);
            if (k < K) v = Bg[i];
            Bsh[i] = v;
        }
    }
    // A tile
    if (MODE == 1) {
        const float4* Ag = (const float4*)A;
        const float4* sc4 = (const float4*)d_scale;
        for (int i = tid; i < 64 * 32; i += 256) {
            int r = i >> 5, k4 = i & 31;
            int gr = rowBase + r;
            float4 v = make_float4(0.f, 0.f, 0.f, 0.f);
            if (gr < N) v = Ag[(size_t)gr * 32 + k4];
            if (BNA) {
                float4 s = sc4[k4], b = sc4[32 + k4];
                v.x = fmaxf(fmaf(v.x, s.x, b.x), 0.f);
                v.y = fmaxf(fmaf(v.y, s.y, b.y), 0.f);
                v.z = fmaxf(fmaf(v.z, s.z, b.z), 0.f);
                v.w = fmaxf(fmaf(v.w, s.w, b.w), 0.f);
            }
            *(float4*)&As[r * lda + k4 * 4] = v;
        }
    } else {
        for (int i = tid; i < 64 * Kp; i += 256) {
            int r = i / Kp, k = i - r * Kp;
            int gr = rowBase + r;
            As[r * lda + k] = (k < K && gr < N) ? A[(size_t)gr * K + k] : 0.0f;
        }
    }
    __syncthreads();

    int tx = tid & 31;   // cols 4*tx .. 4*tx+3
    int ty = tid >> 5;   // rows 8*ty .. 8*ty+7
    const float* Arow = As + (ty * 8) * lda;
    const float4* Bv = (const float4*)Bs;

    float acc[8][4];
#pragma unroll
    for (int i = 0; i < 8; i++) { acc[i][0] = acc[i][1] = acc[i][2] = acc[i][3] = 0.0f; }

#pragma unroll 2
    for (int k = 0; k < Kp; k += 4) {
        float4 b0 = Bv[(k + 0) * 32 + tx];
        float4 b1 = Bv[(k + 1) * 32 + tx];
        float4 b2 = Bv[(k + 2) * 32 + tx];
        float4 b3 = Bv[(k + 3) * 32 + tx];
#pragma unroll
        for (int i = 0; i < 8; i++) {
            float4 a = *(const float4*)&Arow[i * lda + k];  // warp-broadcast LDS.128
            acc[i][0] = fmaf(a.x, b0.x, acc[i][0]);
            acc[i][1] = fmaf(a.x, b0.y, acc[i][1]);
            acc[i][2] = fmaf(a.x, b0.z, acc[i][2]);
            acc[i][3] = fmaf(a.x, b0.w, acc[i][3]);
            acc[i][0] = fmaf(a.y, b1.x, acc[i][0]);
            acc[i][1] = fmaf(a.y, b1.y, acc[i][1]);
            acc[i][2] = fmaf(a.y, b1.z, acc[i][2]);
            acc[i][3] = fmaf(a.y, b1.w, acc[i][3]);
            acc[i][0] = fmaf(a.z, b2.x, acc[i][0]);
            acc[i][1] = fmaf(a.z, b2.y, acc[i][1]);
            acc[i][2] = fmaf(a.z, b2.z, acc[i][2]);
            acc[i][3] = fmaf(a.z, b2.w, acc[i][3]);
            acc[i][0] = fmaf(a.w, b3.x, acc[i][0]);
            acc[i][1] = fmaf(a.w, b3.y, acc[i][1]);
            acc[i][2] = fmaf(a.w, b3.z, acc[i][2]);
            acc[i][3] = fmaf(a.w, b3.w, acc[i][3]);
        }
    }

    float4 bb = ((const float4*)bias)[tx];
#pragma unroll
    for (int i = 0; i < 8; i++) {
        int gr = rowBase + ty * 8 + i;
        if (gr >= N) continue;
        if (MODE == 0) {
            float4 o;
            o.x = fmaxf(acc[i][0] + bb.x, 0.f);
            o.y = fmaxf(acc[i][1] + bb.y, 0.f);
            o.z = fmaxf(acc[i][2] + bb.z, 0.f);
            o.w = fmaxf(acc[i][3] + bb.w, 0.f);
            *(float4*)&C[(size_t)gr * H + tx * 4] = o;
        } else {
            float4 hw = make_float4(acc[i][0], acc[i][1], acc[i][2], acc[i][3]);
            *(float4*)&d_hw[(size_t)gr * H + tx * 4] = hw;
            float dv = d_dinv[gr];
            float w = dv * dv;
            float4 o;
            o.x = fmaf(hw.x, w, bb.x); o.y = fmaf(hw.y, w, bb.y);
            o.z = fmaf(hw.z, w, bb.z); o.w = fmaf(hw.w, w, bb.w);
            *(float4*)&d_hn[(size_t)gr * H + tx * 4] = o;
        }
    }
}

// ---------------- edge scatter: h_next[dst] += hw[src]*norm (warp per edge) ----------------
__global__ void scatter_kernel(const int* __restrict__ ei, int E) {
    unsigned i = blockIdx.x * blockDim.x + threadIdx.x;
    unsigned e = i >> 5;
    if (e >= (unsigned)E) return;
    int lane = i & 31;
    int s = ei[e];
    int d = ei[E + e];
    float nrm = d_dinv[s] * d_dinv[d];
    float4 v = ((const float4*)d_hw)[(size_t)s * 32 + lane];
    float* dst = d_hn + (size_t)d * H + lane * 4;
    asm volatile("red.global.add.v4.f32 [%0], {%1,%2,%3,%4};"
                 :: "l"(dst), "f"(v.x * nrm), "f"(v.y * nrm), "f"(v.z * nrm), "f"(v.w * nrm)
                 : "memory");
}

// ---------------- BatchNorm stats (sum, sumsq per channel) ----------------
__global__ void bn_stats_kernel(int N) {
    int c = threadIdx.x & (H - 1);
    int half = threadIdx.x >> 7;  // 0/1
    int base = blockIdx.x * 512;
    int end = min(base + 512, N);
    float s = 0.0f, q = 0.0f;
    for (int r = base + half; r < end; r += 2) {
        float v = d_hn[(size_t)r * H + c];
        s += v; q += v * v;
    }
    __shared__ float sh[512];
    sh[threadIdx.x] = s;
    sh[256 + threadIdx.x] = q;
    __syncthreads();
    if (threadIdx.x < H) {
        atomicAdd(&d_bnstats[c], sh[c] + sh[H + c]);
        atomicAdd(&d_bnstats[H + c], sh[256 + c] + sh[256 + H + c]);
    }
}

__global__ void bn_finalize_kernel(const float* __restrict__ gamma,
                                   const float* __restrict__ beta, float invN) {
    int c = threadIdx.x;
    float mean = d_bnstats[c] * invN;
    float var = d_bnstats[H + c] * invN - mean * mean;
    float sc = gamma[c] * rsqrtf(var + 1e-5f);
    d_scale[c] = sc;
    d_scale[H + c] = beta[c] - mean * sc;
}

// ---------------- pooling (mean + max per graph), fused BN+ReLU of last layer ----------------
__global__ void pool_init_kernel(int G) {
    int i = blockIdx.x * blockDim.x + threadIdx.x;
    if (i < G * H) { d_gsum[i] = 0.0f; d_gmax[i] = 0; }  // 0 == __float_as_int(0.0f)
    if (i < G) d_gcnt[i] = 0.0f;
}

__global__ void pool_kernel(const int* __restrict__ batch, int N) {
    unsigned i = blockIdx.x * blockDim.x + threadIdx.x;
    unsigned n = i >> 5;
    if (n >= (unsigned)N) return;
    int lane = i & 31;
    int b = batch[n];
    float4 v  = ((const float4*)d_hn)[(size_t)n * 32 + lane];
    float4 sc = ((const float4*)d_scale)[lane];
    float4 sh = ((const float4*)d_scale)[32 + lane];
    v.x = fmaxf(fmaf(v.x, sc.x, sh.x), 0.f);
    v.y = fmaxf(fmaf(v.y, sc.y, sh.y), 0.f);
    v.z = fmaxf(fmaf(v.z, sc.z, sh.z), 0.f);
    v.w = fmaxf(fmaf(v.w, sc.w, sh.w), 0.f);
    float* dst = d_gsum + (size_t)b * H + lane * 4;
    asm volatile("red.global.add.v4.f32 [%0], {%1,%2,%3,%4};"
                 :: "l"(dst), "f"(v.x), "f"(v.y), "f"(v.z), "f"(v.w) : "memory");
    int* mdst = d_gmax + (size_t)b * H + lane * 4;
    atomicMax(mdst + 0, __float_as_int(v.x));  // values >= 0 post-ReLU: int order == float order
    atomicMax(mdst + 1, __float_as_int(v.y));
    atomicMax(mdst + 2, __float_as_int(v.z));
    atomicMax(mdst + 3, __float_as_int(v.w));
    if (lane == 0) atomicAdd(&d_gcnt[b], 1.0f);
}

// ---------------- MLP head: one block per graph ----------------
__global__ void __launch_bounds__(128)
mlp_kernel(const float* __restrict__ w1, const float* __restrict__ b1,
           const float* __restrict__ w2, const float* __restrict__ b2,
           const float* __restrict__ w3, const float* __restrict__ b3,
           float* __restrict__ out) {
    int g = blockIdx.x, t = threadIdx.x;
    __shared__ float gs[2 * H], h1s[H], h2s[64];
    float inv = 1.0f / fmaxf(d_gcnt[g], 1.0f);
    gs[t]     = d_gsum[(size_t)g * H + t] * inv;
    gs[H + t] = __int_as_float(d_gmax[(size_t)g * H + t]);
    __syncthreads();
    float a = b1[t];
#pragma unroll 8
    for (int k = 0; k < 2 * H; k++) a = fmaf(gs[k], w1[k * H + t], a);
    h1s[t] = fmaxf(a, 0.0f);
    __syncthreads();
    if (t < 64) {
        float a2 = b2[t];
#pragma unroll 8
        for (int k = 0; k < H; k++) a2 = fmaf(h1s[k], w2[k * 64 + t], a2);
        h2s[t] = fmaxf(a2, 0.0f);
    }
    __syncthreads();
    if (t < 32) {
        float s = h2s[t] * w3[t] + h2s[t + 32] * w3[t + 32];
        for (int o = 16; o; o >>= 1) s += __shfl_down_sync(0xffffffffu, s, o);
        if (t == 0) out[g] = s + b3[0];
    }
}

// ---------------- launch ----------------
extern "C" void kernel_launch(void* const* d_in, const int* in_sizes, int n_in,
                              void* d_out, int out_size) {
    const float* x      = (const float*)d_in[0];
    const int*   ei     = (const int*)  d_in[1];
    const int*   batch  = (const int*)  d_in[2];
    const float* emb_W  = (const float*)d_in[3];
    const float* emb_b  = (const float*)d_in[4];
    const float* conv_W = (const float*)d_in[5];
    const float* conv_b = (const float*)d_in[6];
    const float* bn_g   = (const float*)d_in[7];
    const float* bn_b   = (const float*)d_in[8];
    const float* w1     = (const float*)d_in[9];
    const float* b1     = (const float*)d_in[10];
    const float* w2     = (const float*)d_in[11];
    const float* b2     = (const float*)d_in[12];
    const float* w3     = (const float*)d_in[13];
    const float* b3     = (const float*)d_in[14];
    float* out = (float*)d_out;

    int N = in_sizes[0] / FIN;
    int E = in_sizes[1] / 2;
    int G = out_size;
    int n4 = N * 32;  // float4 count of an [N,128] buffer

    float *ph = nullptr, *phn = nullptr;
    cudaGetSymbolAddress((void**)&ph, d_h);
    cudaGetSymbolAddress((void**)&phn, d_hn);

    // emb: K=74, Kp=76, lda=80 ; conv: K=128, Kp=128, lda=132
    const int embK = FIN, embKp = 76, embLda = 80;
    const int cvK = H, cvKp = H, cvLda = H + 4;
    size_t embSm = (size_t)(64 * embLda + embKp * H) * sizeof(float);  // ~58 KB
    size_t cvSm  = (size_t)(64 * cvLda + cvKp * H) * sizeof(float);    // ~97 KB
    cudaFuncSetAttribute(gemm_kernel<0, false>,
                         cudaFuncAttributeMaxDynamicSharedMemorySize, (int)embSm);
    cudaFuncSetAttribute(gemm_kernel<1, false>,
                         cudaFuncAttributeMaxDynamicSharedMemorySize, (int)cvSm);
    cudaFuncSetAttribute(gemm_kernel<1, true>,
                         cudaFuncAttributeMaxDynamicSharedMemorySize, (int)cvSm);

    // degrees & normalization
    deg_init_kernel<<<(N + 255) / 256, 256>>>(N);
    deg_edge_kernel<<<(E + 255) / 256, 256>>>(ei, E);
    deg_fin_kernel<<<(N + 255) / 256, 256>>>(N);

    // embedding: d_h = relu(x @ emb_W + emb_b)
    gemm_kernel<0, false><<<(N + 63) / 64, 256, embSm>>>(
        x, emb_W, emb_b, ph, N, embK, embKp, embLda);

    // GCN layers
    int grid = (N + 63) / 64;
    for (int l = 0; l < 3; l++) {
        if (l == 0) {
            gemm_kernel<1, false><<<grid, 256, cvSm>>>(
                ph, conv_W, conv_b, nullptr, N, cvK, cvKp, cvLda);
        } else {
            // A = d_hn (prev layer, pre-BN); BN+ReLU fused into A load
            gemm_kernel<1, true><<<grid, 256, cvSm>>>(
                phn, conv_W + (size_t)l * H * H, conv_b + (size_t)l * H,
                nullptr, N, cvK, cvKp, cvLda);
        }
        scatter_kernel<<<(E * 32 + 255) / 256, 256>>>(ei, E);
        zero_stats_kernel<<<1, 256>>>();
        bn_stats_kernel<<<(N + 511) / 512, 256>>>(N);
        bn_finalize_kernel<<<1, H>>>(bn_g + l * H, bn_b + l * H, 1.0f / (float)N);
    }

    // pooling (BN+ReLU of last layer fused) + head
    pool_init_kernel<<<(G * H + 255) / 256, 256>>>(G);
    pool_kernel<<<(n4 + 255) / 256, 256>>>(batch, N);
    mlp_kernel<<<G, H>>>(w1, b1, w2, b2, w3, b3, out);
}